// round 12
// baseline (speedup 1.0000x reference)
#include <cuda_runtime.h>
#include <cuda_bf16.h>
#include <cstdint>
#include <math.h>

#define NB 96
#define NC 64
#define NN 512
#define NO 64

typedef unsigned long long ull;

// ---------------- scratch (device globals; no allocation) ----------------
__device__ float g_x0 [NB*NC*NN];
__device__ float g_x1 [NB*NC*NN];
__device__ float g_x1e[NB*NC*NN];
__device__ float g_PQ [NB*2*NO*NN];   // per batch: Pt[512][64] then Qt[512][64]
__device__ int   g_i10[NB*NN*10];
__device__ int   g_i8 [NB*NN*8];
__device__ float g_f  [NB*NN];
__device__ float g_msk[NB*NN];
__device__ float g_part[NB*4*128];    // per (b, jq): 0..63 max, 64..127 sum

// ---------------- f32x2 helpers (SASS FFMA2 — PTX-only) ----------------
__device__ __forceinline__ void fma2(ull& acc, ull a, ull b) {
    asm("fma.rn.f32x2 %0, %1, %2, %0;" : "+l"(acc) : "l"(a), "l"(b));
}
__device__ __forceinline__ ull pk2(float lo, float hi) {
    ull r;
    asm("mov.b64 %0, {%1, %2};" : "=l"(r) : "f"(lo), "f"(hi));
    return r;
}
__device__ __forceinline__ float2 upk(ull v) {
    float2 r;
    asm("mov.b64 {%0, %1}, %2;" : "=f"(r.x), "=f"(r.y) : "l"(v));
    return r;
}

// ---------------- mma.sync helpers (sm_80+ path, legal on base sm_103) ----------------
__device__ __forceinline__ uint32_t smem_u32(const void* p) {
    uint32_t a;
    asm("{ .reg .u64 t; cvta.to.shared.u64 t, %1; cvt.u32.u64 %0, t; }" : "=r"(a) : "l"(p));
    return a;
}
__device__ __forceinline__ void ldm4(uint32_t* r, uint32_t a) {
    asm volatile("ldmatrix.sync.aligned.m8n8.x4.shared.b16 {%0,%1,%2,%3}, [%4];"
                 : "=r"(r[0]), "=r"(r[1]), "=r"(r[2]), "=r"(r[3]) : "r"(a));
}
__device__ __forceinline__ void ldm2(uint32_t* r, uint32_t a) {
    asm volatile("ldmatrix.sync.aligned.m8n8.x2.shared.b16 {%0,%1}, [%2];"
                 : "=r"(r[0]), "=r"(r[1]) : "r"(a));
}
__device__ __forceinline__ void mma16816(float* c, const uint32_t* a, const uint32_t* b) {
    asm volatile("mma.sync.aligned.m16n8k16.row.col.f32.bf16.bf16.f32 "
                 "{%0,%1,%2,%3}, {%4,%5,%6,%7}, {%8,%9}, {%0,%1,%2,%3};"
                 : "+f"(c[0]), "+f"(c[1]), "+f"(c[2]), "+f"(c[3])
                 : "r"(a[0]), "r"(a[1]), "r"(a[2]), "r"(a[3]), "r"(b[0]), "r"(b[1]));
}

// ---------------- kernel 1: erase0 (x -> x0) + temporal shift (x -> x1seq) ----------------
__global__ __launch_bounds__(256) void k_prep(const float* __restrict__ x,
    const float* __restrict__ w_e, const float* __restrict__ b_e,
    const float* __restrict__ g_e, const float* __restrict__ be_e,
    const float* __restrict__ m_e, const float* __restrict__ v_e)
{
    int b = blockIdx.x, tid = threadIdx.x;
    __shared__ float res[NC];
    __shared__ float yb[NC];
    const float* xb = x + (size_t)b*NC*NN;

    int ch = tid >> 2, lane = tid & 3;
    float s = 0.f;
    for (int i = lane; i < NN; i += 4) s += xb[ch*NN + i];
    s += __shfl_down_sync(0xffffffffu, s, 1, 4);
    s += __shfl_down_sync(0xffffffffu, s, 2, 4);
    if (lane == 0) res[ch] = s * (1.0f/NN);
    __syncthreads();

    if (tid < NC) {
        float y = b_e[tid];
        for (int c = 0; c < NC; c++) y = fmaf(w_e[tid*NC + c], res[c], y);
        float sc = g_e[tid] * rsqrtf(v_e[tid] + 1e-5f);
        yb[tid] = (y - m_e[tid]) * sc + be_e[tid];
    }
    __syncthreads();

    int ti = b % 12;
    int tshift = (ti + 1 < 11) ? (ti + 1) : 11;
    int srcb = b - ti + tshift;
    const float* xsft = x + (size_t)srcb*NC*NN;
    float* x0 = g_x0 + (size_t)b*NC*NN;
    float* x1 = g_x1 + (size_t)b*NC*NN;
    for (int idx = tid; idx < NC*NN; idx += 256) {
        int c = idx >> 9;
        x0[idx] = xb[idx] + yb[c];
        x1[idx] = xsft[idx];
    }
}

// ---------------- kernel 2: HMMA kNN (bf16-split Gram + fused top-K) ----------------
// grid (96, 4): block = (batch, 128-query tile), 256 threads, 8 warps (16-row band each).
// smem: B[512][272B] (hi 128B | lo 128B | 16B pad) | xx[512] f32 | cand[128][4][K] ull
#define SMB_OFF  0
#define SMXX_OFF 139264
#define SMC_OFF  141312
#define KNN_MMA_SMEM (141312 + 128*4*10*8)   // 182272 (K=10 worst case)

template<int K>
__global__ __launch_bounds__(256) void k_knn_mma(int sel)
{
    extern __shared__ char smem[];
    uint32_t sb = smem_u32(smem);
    float* xxs = (float*)(smem + SMXX_OFF);
    int b = blockIdx.x, itile = blockIdx.y, tid = threadIdx.x;
    const float* xb = ((sel == 0) ? g_x0 : ((sel == 1) ? g_x1 : g_x1e)) + (size_t)b*NC*NN;
    int* idxout = ((K == 10) ? g_i10 : g_i8) + (size_t)b*NN*K;

    // ---- convert all 512 points to bf16 hi/lo (STS.128, conflict-free) + exact fp32 xx
    #pragma unroll
    for (int rr = 0; rr < 2; rr++) {
        int r = tid + rr*256;
        char* rowp = smem + SMB_OFF + r*272;
        float acc = 0.f;
        #pragma unroll
        for (int chk = 0; chk < 8; chk++) {
            float v[8];
            #pragma unroll
            for (int u = 0; u < 8; u++) {
                v[u] = xb[(chk*8 + u)*NN + r];              // coalesced across threads
                acc = fmaf(v[u], v[u], acc);
            }
            uint32_t hi[4], lo[4];
            #pragma unroll
            for (int u = 0; u < 4; u++) {
                float f0 = v[2*u], f1 = v[2*u+1];
                __nv_bfloat16 h0 = __float2bfloat16(f0), h1 = __float2bfloat16(f1);
                __nv_bfloat16 l0 = __float2bfloat16(f0 - __bfloat162float(h0));
                __nv_bfloat16 l1 = __float2bfloat16(f1 - __bfloat162float(h1));
                hi[u] = (uint32_t)__bfloat16_as_ushort(h0) | ((uint32_t)__bfloat16_as_ushort(h1) << 16);
                lo[u] = (uint32_t)__bfloat16_as_ushort(l0) | ((uint32_t)__bfloat16_as_ushort(l1) << 16);
            }
            *(uint4*)(rowp + chk*16)       = make_uint4(hi[0], hi[1], hi[2], hi[3]);
            *(uint4*)(rowp + 128 + chk*16) = make_uint4(lo[0], lo[1], lo[2], lo[3]);
        }
        xxs[r] = acc;
    }
    __syncthreads();

    int lane = tid & 31, w = tid >> 5;
    int lr = lane & 7, s = lane >> 3;

    // ---- preload A fragments (row band is a slice of the B buffer)
    uint32_t ahi[4][4], alo[4][4];
    {
        uint32_t arow = (uint32_t)(itile*128 + w*16 + lr + ((s & 1) << 3));
        uint32_t abase = sb + SMB_OFF + arow*272 + ((s >> 1) << 4);
        #pragma unroll
        for (int kt = 0; kt < 4; kt++) {
            ldm4(ahi[kt], abase + kt*32);
            ldm4(alo[kt], abase + 128 + kt*32);
        }
    }
    int r0 = itile*128 + w*16 + (lane >> 2);     // this lane's rows: r0, r0+8 (global-in-batch)
    float xxi0 = xxs[r0], xxi1 = xxs[r0 + 8];

    float bv0[K]; int bi0[K]; float bv1[K]; int bi1[K];
    #pragma unroll
    for (int q = 0; q < K; q++) { bv0[q] = -3e38f; bi0[q] = 0; bv1[q] = -3e38f; bi1[q] = 0; }

    uint32_t bbase = sb + SMB_OFF + lr*272 + (((lane >> 3) & 1) << 4);

    for (int ct = 0; ct < 64; ct++) {
        float c[4] = {0.f, 0.f, 0.f, 0.f};
        uint32_t bb_ = bbase + (uint32_t)ct * (8*272);
        #pragma unroll
        for (int kt = 0; kt < 4; kt++) {
            uint32_t bh[2], bl[2];
            ldm2(bh, bb_ + kt*32);                // B hi
            mma16816(c, ahi[kt], bh);             // hi·hi
            mma16816(c, alo[kt], bh);             // lo·hi
            ldm2(bl, bb_ + 128 + kt*32);          // B lo
            mma16816(c, ahi[kt], bl);             // hi·lo   (lo·lo dropped, ~2^-18)
        }
        int j0 = ct*8 + (lane & 3)*2;
        float2 xc = *(const float2*)(smem + SMXX_OFF + j0*4);
        float pd00 = 2.f*c[0] - xxi0 - xc.x;
        float pd01 = 2.f*c[1] - xxi0 - xc.y;
        float pd10 = 2.f*c[2] - xxi1 - xc.x;
        float pd11 = 2.f*c[3] - xxi1 - xc.y;
        #define INS(BV, BI, V, ID) \
            if ((V) > BV[K-1]) { \
                float _v = (V); int _id = (ID); \
                _Pragma("unroll") \
                for (int q = 0; q < K; q++) { \
                    if (_v > BV[q]) { \
                        float tv = BV[q]; int tq = BI[q]; \
                        BV[q] = _v; BI[q] = _id; _v = tv; _id = tq; \
                    } \
                } \
            }
        INS(bv0, bi0, pd00, j0); INS(bv0, bi0, pd01, j0+1);
        INS(bv1, bi1, pd10, j0); INS(bv1, bi1, pd11, j0+1);
        #undef INS
    }

    // ---- spill per-lane candidates: cand[row_local][laneq][K]
    {
        int rl0 = w*16 + (lane >> 2), t = lane & 3;
        ull* c0p = (ull*)(smem + SMC_OFF) + ((size_t)rl0*4 + t)*K;
        ull* c1p = (ull*)(smem + SMC_OFF) + ((size_t)(rl0+8)*4 + t)*K;
        #pragma unroll
        for (int q = 0; q < K; q++) {
            c0p[q] = (ull)__float_as_uint(bv0[q]) | ((ull)(uint32_t)bi0[q] << 32);
            c1p[q] = (ull)__float_as_uint(bv1[q]) | ((ull)(uint32_t)bi1[q] << 32);
        }
    }
    __syncthreads();

    // ---- merge 4 lanes' lists per row (tie -> lowest index, matching top_k)
    if (tid < 128) {
        const ull* basep = (ull*)(smem + SMC_OFF) + (size_t)tid*4*K;
        float bv[K]; int bi[K];
        #pragma unroll
        for (int q = 0; q < K; q++) { bv[q] = -3e38f; bi[q] = 0x7fffffff; }
        for (int e = 0; e < 4*K; e++) {
            ull u = basep[e];
            float v = __uint_as_float((uint32_t)u);
            int id = (int)(u >> 32);
            if (v > bv[K-1] || (v == bv[K-1] && id < bi[K-1])) {
                #pragma unroll
                for (int q = 0; q < K; q++) {
                    if (v > bv[q] || (v == bv[q] && id < bi[q])) {
                        float tv = bv[q]; int tq = bi[q];
                        bv[q] = v; bi[q] = id; v = tv; id = tq;
                    }
                }
            }
        }
        int* op = idxout + (size_t)(itile*128 + tid)*K;
        #pragma unroll
        for (int q = 0; q < K; q++) op[q] = bi[q];
    }
}

// ---------------- kernel 3: P'/Q' GEMM (BN folded), FFMA2, TRANSPOSED output ----------------
__global__ __launch_bounds__(256) void k_pq(int sel,
    const float* __restrict__ w, const float* __restrict__ gg,
    const float* __restrict__ bb, const float* __restrict__ mm,
    const float* __restrict__ vv)
{
    extern __shared__ float smp[];
    float* xs2   = smp;            // [64][128] x tile
    float* W2    = smp + 8192;     // [128][64] fused weights
    float* bias2 = smp + 16384;    // [128]
    float* sarr  = bias2 + 128;    // [64]
    const float* xin = (sel == 0) ? g_x0 : g_x1e;

    int b = blockIdx.x, jq = blockIdx.y, tid = threadIdx.x;
    if (tid < 64) sarr[tid] = gg[tid] * rsqrtf(vv[tid] + 1e-5f);
    __syncthreads();

    for (int idx = tid; idx < 128*64; idx += 256) {
        int r = idx >> 6, c = idx & 63;
        float val;
        if (r < 64) val = sarr[r] * w[r*128 + c];
        else { int o = r - 64; val = sarr[o] * (w[o*128 + 64 + c] - w[o*128 + c]); }
        W2[idx] = val;
    }
    if (tid < 128)
        bias2[tid] = (tid < 64) ? 0.f : (bb[tid-64] - mm[tid-64]*sarr[tid-64]);

    const float* xb = xin + (size_t)b*NC*NN + jq*128;
    for (int idx = tid; idx < 64*128; idx += 256) {
        int c = idx >> 7, jj = idx & 127;
        xs2[idx] = xb[c*NN + jj];
    }
    __syncthreads();

    int rt = tid >> 4, ct = tid & 15;
    int r0 = rt*8, j0 = ct*8;
    ull accp[8][4];
    #pragma unroll
    for (int u = 0; u < 8; u++)
        #pragma unroll
        for (int vp = 0; vp < 4; vp++) accp[u][vp] = 0ull;

    for (int kk = 0; kk < 64; kk++) {
        ull wp[8];
        #pragma unroll
        for (int u = 0; u < 8; u++) {
            float wv = W2[(r0+u)*64 + kk];
            wp[u] = pk2(wv, wv);
        }
        const ulonglong2* xp = (const ulonglong2*)(xs2 + kk*128 + j0);
        ulonglong2 xa = xp[0], xc = xp[1];
        #pragma unroll
        for (int u = 0; u < 8; u++) {
            fma2(accp[u][0], wp[u], xa.x);
            fma2(accp[u][1], wp[u], xa.y);
            fma2(accp[u][2], wp[u], xc.x);
            fma2(accp[u][3], wp[u], xc.y);
        }
    }

    float a[8][8];
    #pragma unroll
    for (int u = 0; u < 8; u++) {
        float bsv = bias2[r0+u];
        #pragma unroll
        for (int vp = 0; vp < 4; vp++) {
            float2 t = upk(accp[u][vp]);
            a[u][2*vp]   = t.x + bsv;
            a[u][2*vp+1] = t.y + bsv;
        }
    }

    float* Ptb = g_PQ + (size_t)b*2*NO*NN;      // [512][64]
    float* Qtb = Ptb + (size_t)NN*NO;           // [512][64]
    #pragma unroll
    for (int v = 0; v < 8; v++) {
        int j = jq*128 + j0 + v;
        float* dst = (r0 < 64) ? (Ptb + (size_t)j*64 + r0)
                               : (Qtb + (size_t)j*64 + (r0-64));
        float4 o0 = make_float4(a[0][v], a[1][v], a[2][v], a[3][v]);
        float4 o1 = make_float4(a[4][v], a[5][v], a[6][v], a[7][v]);
        *(float4*)(dst)     = o0;
        *(float4*)(dst + 4) = o1;
    }
}

// ---------------- kernel 4: gather-max over k + lrelu + partial max/mean ----------------
__global__ __launch_bounds__(256) void k_gmax()
{
    int b = blockIdx.x, jq = blockIdx.y, tid = threadIdx.x;
    int w = tid >> 5, l = tid & 31;
    const float* Pt = g_PQ + (size_t)b*2*NO*NN;
    const float* Qt = Pt + (size_t)NN*NO;
    const int* ig = g_i10 + (size_t)b*NN*10;

    float mx0 = -3e38f, mx1 = -3e38f, s0 = 0.f, s1 = 0.f;
    #pragma unroll 2
    for (int p = 0; p < 16; p++) {
        int i = jq*128 + w*16 + p;
        const int* ip = ig + (size_t)i*10;
        float a0 = -3e38f, a1 = -3e38f;
        #pragma unroll
        for (int kk = 0; kk < 10; kk++) {
            int nb = ip[kk];                               // uniform -> broadcast
            float2 pv = *(const float2*)(Pt + (size_t)nb*64 + 2*l);
            a0 = fmaxf(a0, pv.x);
            a1 = fmaxf(a1, pv.y);
        }
        float2 q = *(const float2*)(Qt + (size_t)i*64 + 2*l);
        float y0 = a0 + q.x; y0 = (y0 > 0.f) ? y0 : 0.2f*y0;
        float y1 = a1 + q.y; y1 = (y1 > 0.f) ? y1 : 0.2f*y1;
        mx0 = fmaxf(mx0, y0); s0 += y0;
        mx1 = fmaxf(mx1, y1); s1 += y1;
    }

    __shared__ float sred[8][128];
    sred[w][2*l]      = mx0;
    sred[w][2*l+1]    = mx1;
    sred[w][64+2*l]   = s0;
    sred[w][64+2*l+1] = s1;
    __syncthreads();
    if (tid < 128) {
        float v;
        if (tid < 64) {
            v = sred[0][tid];
            #pragma unroll
            for (int ww = 1; ww < 8; ww++) v = fmaxf(v, sred[ww][tid]);
        } else {
            v = sred[0][tid];
            #pragma unroll
            for (int ww = 1; ww < 8; ww++) v += sred[ww][tid];
        }
        g_part[((size_t)b*4 + jq)*128 + tid] = v;
    }
}

// ---------------- kernel 4b: final reduction over the 4 point-chunks ----------------
__global__ __launch_bounds__(128) void k_fin(float* __restrict__ out, int accumulate)
{
    int b = blockIdx.x, tid = threadIdx.x;
    const float* pp = g_part + (size_t)b*4*128;
    float v;
    if (tid < 64) {
        v = pp[tid];
        #pragma unroll
        for (int jq = 1; jq < 4; jq++) v = fmaxf(v, pp[jq*128 + tid]);
    } else {
        v = pp[tid];
        #pragma unroll
        for (int jq = 1; jq < 4; jq++) v += pp[jq*128 + tid];
        v *= (1.0f/NN);
    }
    if (accumulate) out[b*128 + tid] += v;
    else            out[b*128 + tid]  = v;
}

// ---------------- kernel 5: corre_binar (q, f, fk, argmax, masks) ----------------
__global__ __launch_bounds__(512) void k_corre(const float* __restrict__ w_red,
                                               const float* __restrict__ outv)
{
    __shared__ float qv[64];
    __shared__ float fs[NN];
    __shared__ float rv[NN];
    __shared__ int   ri[NN];
    int b = blockIdx.x, tid = threadIdx.x;
    if (tid < 64) {
        const float* xv = outv + b*128;    // x0_vec == p0 max-half
        float a = 0.f;
        for (int c = 0; c < 64; c++) a = fmaf(w_red[tid*64 + c], xv[c], a);
        qv[tid] = a;
    }
    __syncthreads();
    const float* x1b = g_x1 + (size_t)b*NC*NN;
    float f = 0.f;
    for (int c = 0; c < 64; c++) f = fmaf(qv[c], x1b[c*NN + tid], f);
    f *= 0.125f;
    fs[tid] = f;
    g_f[b*NN + tid] = f;
    __syncthreads();
    const int* i8 = g_i8 + ((size_t)b*NN + tid)*8;
    float fk = f;
    #pragma unroll
    for (int kk = 0; kk < 8; kk++) fk += fs[i8[kk]];
    rv[tid] = fk; ri[tid] = tid;
    __syncthreads();
    for (int s2 = 256; s2 > 0; s2 >>= 1) {   // argmax, ties -> lowest index
        if (tid < s2) {
            float a = rv[tid], b2 = rv[tid + s2];
            int ia = ri[tid], ib2 = ri[tid + s2];
            if (b2 > a || (b2 == a && ib2 < ia)) { rv[tid] = b2; ri[tid] = ib2; }
        }
        __syncthreads();
    }
    int widx = ri[0];
    g_msk[b*NN + tid] = 1.0f;
    __syncthreads();
    if (tid == 0) g_msk[b*NN + widx] = 0.f;
    if (tid < 8)  g_msk[b*NN + g_i8[((size_t)b*NN + widx)*8 + tid]] = 0.f;
}

// ---------------- kernel 6: erase1 (masked softmax attention + conv_erase) ----------------
__global__ __launch_bounds__(512) void k_erase1(
    const float* __restrict__ w_e, const float* __restrict__ b_e,
    const float* __restrict__ g_e, const float* __restrict__ be_e,
    const float* __restrict__ m_e, const float* __restrict__ v_e)
{
    __shared__ float smw[NN];
    __shared__ float red[NN];
    __shared__ float msk[NN];
    __shared__ float res[64];
    __shared__ float yb[64];
    int b = blockIdx.x, tid = threadIdx.x;
    const float* x1b = g_x1 + (size_t)b*NC*NN;

    float M = g_msk[b*NN + tid];
    float f = g_f[b*NN + tid];
    msk[tid] = M;
    float z = f - (1.0f - M)*1e8f;
    red[tid] = z;
    __syncthreads();
    for (int s2 = 256; s2 > 0; s2 >>= 1) {
        if (tid < s2) red[tid] = fmaxf(red[tid], red[tid + s2]);
        __syncthreads();
    }
    float zmax = red[0];
    __syncthreads();
    float e = expf(z - zmax);
    red[tid] = e;
    __syncthreads();
    for (int s2 = 256; s2 > 0; s2 >>= 1) {
        if (tid < s2) red[tid] += red[tid + s2];
        __syncthreads();
    }
    float esum = red[0];
    smw[tid] = e / esum;
    __syncthreads();

    int ch = tid >> 3, ln = tid & 7;
    float a = 0.f;
    for (int i = ln; i < NN; i += 8) a = fmaf(x1b[ch*NN + i], smw[i], a);
    a += __shfl_down_sync(0xffffffffu, a, 1, 8);
    a += __shfl_down_sync(0xffffffffu, a, 2, 8);
    a += __shfl_down_sync(0xffffffffu, a, 4, 8);
    if (ln == 0) res[ch] = a;
    __syncthreads();

    if (tid < 64) {
        float y = b_e[tid];
        for (int c = 0; c < 64; c++) y = fmaf(w_e[tid*64 + c], res[c], y);
        float sc = g_e[tid]*rsqrtf(v_e[tid] + 1e-5f);
        yb[tid] = (y - m_e[tid])*sc + be_e[tid];
    }
    __syncthreads();

    float* xo = g_x1e + (size_t)b*NC*NN;
    for (int idx = tid; idx < NC*NN; idx += 512) {
        int c = idx >> 9, i = idx & 511;
        xo[idx] = x1b[idx]*msk[i] + yb[c];
    }
}

// ---------------- launcher ----------------
extern "C" void kernel_launch(void* const* d_in, const int* in_sizes, int n_in,
                              void* d_out, int out_size)
{
    const float* x        = (const float*)d_in[0];
    const float* w_reduce = (const float*)d_in[1];
    const float* w_erase  = (const float*)d_in[2];
    const float* b_erase  = (const float*)d_in[3];
    const float* g_erase  = (const float*)d_in[4];
    const float* be_erase = (const float*)d_in[5];
    const float* m_erase  = (const float*)d_in[6];
    const float* v_erase  = (const float*)d_in[7];
    const float* w0 = (const float*)d_in[8];
    const float* g0 = (const float*)d_in[9];
    const float* b0 = (const float*)d_in[10];
    const float* m0 = (const float*)d_in[11];
    const float* v0 = (const float*)d_in[12];
    const float* w1 = (const float*)d_in[13];
    const float* g1 = (const float*)d_in[14];
    const float* b1 = (const float*)d_in[15];
    const float* m1 = (const float*)d_in[16];
    const float* v1 = (const float*)d_in[17];
    float* out = (float*)d_out;

    const int PQ_SMEM = (8192 + 8192 + 128 + 64)*4;  // 65792 B
    cudaFuncSetAttribute(k_knn_mma<10>, cudaFuncAttributeMaxDynamicSharedMemorySize, KNN_MMA_SMEM);
    cudaFuncSetAttribute(k_knn_mma<8>,  cudaFuncAttributeMaxDynamicSharedMemorySize, KNN_MMA_SMEM);
    cudaFuncSetAttribute(k_pq,          cudaFuncAttributeMaxDynamicSharedMemorySize, PQ_SMEM);

    k_prep<<<NB, 256>>>(x, w_erase, b_erase, g_erase, be_erase, m_erase, v_erase);
    k_knn_mma<10><<<dim3(NB,4), 256, KNN_MMA_SMEM>>>(0);       // knn10 on x0 -> g_i10
    k_knn_mma<8> <<<dim3(NB,4), 256, KNN_MMA_SMEM>>>(1);       // knn8 on x1 -> g_i8
    k_pq<<<dim3(NB,4), 256, PQ_SMEM>>>(0, w0, g0, b0, m0, v0); // branch0 Pt/Qt
    k_gmax<<<dim3(NB,4), 256>>>();                             // partials
    k_fin<<<NB, 128>>>(out, 0);                                // p0 -> out (x0_vec)
    k_corre<<<NB, 512>>>(w_reduce, out);                       // masks, f
    k_erase1<<<NB, 512>>>(w_erase, b_erase, g_erase, be_erase, m_erase, v_erase);
    k_knn_mma<10><<<dim3(NB,4), 256, KNN_MMA_SMEM>>>(2);       // knn10 on x1e -> g_i10
    k_pq<<<dim3(NB,4), 256, PQ_SMEM>>>(2, w1, g1, b1, m1, v1); // branch1 Pt/Qt
    k_gmax<<<dim3(NB,4), 256>>>();
    k_fin<<<NB, 128>>>(out, 1);                                // out += p1
}

// round 13
// speedup vs baseline: 1.1419x; 1.1419x over previous
#include <cuda_runtime.h>
#include <cstdint>
#include <math.h>

#define NB 96
#define NC 64
#define NN 512
#define NO 64

typedef unsigned long long ull;

// ---------------- scratch (device globals; no allocation) ----------------
__device__ float g_x0 [NB*NC*NN];
__device__ float g_x1 [NB*NC*NN];
__device__ float g_x1e[NB*NC*NN];
__device__ float g_PQ [NB*2*NO*NN];   // per batch: Pt[512][64] then Qt[512][64]
__device__ float g_f  [NB*NN];
__device__ float g_msk[NB*NN];
__device__ float g_part[NB*4*128];    // per (b, jq): 0..63 max, 64..127 sum
// partial top-k candidates: [b][js][i][K]
__device__ float g_c10v[NB*3*NN*10];
__device__ int   g_c10i[NB*3*NN*10];
__device__ float g_c8v [NB*3*NN*8];
__device__ int   g_c8i [NB*3*NN*8];

// ---------------- f32x2 helpers (SASS FFMA2 — PTX-only) ----------------
__device__ __forceinline__ void fma2(ull& acc, ull a, ull b) {
    asm("fma.rn.f32x2 %0, %1, %2, %0;" : "+l"(acc) : "l"(a), "l"(b));
}
__device__ __forceinline__ ull pk2(float lo, float hi) {
    ull r;
    asm("mov.b64 %0, {%1, %2};" : "=l"(r) : "f"(lo), "f"(hi));
    return r;
}
__device__ __forceinline__ float2 upk(ull v) {
    float2 r;
    asm("mov.b64 {%0, %1}, %2;" : "=f"(r.x), "=f"(r.y) : "l"(v));
    return r;
}

// ---------------- kernel 1: erase0 (x -> x0) + temporal shift (x -> x1seq) ----------------
__global__ __launch_bounds__(256) void k_prep(const float* __restrict__ x,
    const float* __restrict__ w_e, const float* __restrict__ b_e,
    const float* __restrict__ g_e, const float* __restrict__ be_e,
    const float* __restrict__ m_e, const float* __restrict__ v_e)
{
    int b = blockIdx.x, tid = threadIdx.x;
    __shared__ float res[NC];
    __shared__ float yb[NC];
    const float* xb = x + (size_t)b*NC*NN;

    int ch = tid >> 2, lane = tid & 3;
    float s = 0.f;
    for (int i = lane; i < NN; i += 4) s += xb[ch*NN + i];
    s += __shfl_down_sync(0xffffffffu, s, 1, 4);
    s += __shfl_down_sync(0xffffffffu, s, 2, 4);
    if (lane == 0) res[ch] = s * (1.0f/NN);
    __syncthreads();

    if (tid < NC) {
        float y = b_e[tid];
        for (int c = 0; c < NC; c++) y = fmaf(w_e[tid*NC + c], res[c], y);
        float sc = g_e[tid] * rsqrtf(v_e[tid] + 1e-5f);
        yb[tid] = (y - m_e[tid]) * sc + be_e[tid];
    }
    __syncthreads();

    int ti = b % 12;
    int tshift = (ti + 1 < 11) ? (ti + 1) : 11;
    int srcb = b - ti + tshift;
    const float* xsft = x + (size_t)srcb*NC*NN;
    float* x0 = g_x0 + (size_t)b*NC*NN;
    float* x1 = g_x1 + (size_t)b*NC*NN;
    for (int idx = tid; idx < NC*NN; idx += 256) {
        int c = idx >> 9;
        x0[idx] = xb[idx] + yb[c];
        x1[idx] = xsft[idx];
    }
}

// ---------------- kNN partial: 512 threads, one query row each, j-subrange ----------------
template<int K>
__device__ __forceinline__ void knn_part(const float* __restrict__ xb,
                                         float* __restrict__ cv,   // [NN][K] this slice
                                         int*   __restrict__ ci,
                                         int jlo, int jhi,
                                         float* xs, float* xx)
{
    int tid = threadIdx.x;

    {
        int r = tid;
        float acc = 0.f;
        #pragma unroll 8
        for (int cp = 0; cp < NC; cp++) {
            float v = xb[cp*NN + r];
            xs[r*68 + cp] = v;
            acc = fmaf(v, v, acc);
        }
        xx[r] = acc;
    }
    __syncthreads();

    int i = tid;
    ull xiu[32];
    {
        const ulonglong2* xr = (const ulonglong2*)(xs + i*68);
        #pragma unroll
        for (int m = 0; m < 16; m++) {
            ulonglong2 t = xr[m];
            xiu[2*m]   = t.x;
            xiu[2*m+1] = t.y;
        }
    }
    float xxi = xx[i];

    float bv[K]; int bix[K];
    #pragma unroll
    for (int q = 0; q < K; q++) { bv[q] = -3e38f; bix[q] = 0; }

    for (int j = jlo; j < jhi; j += 2) {
        const ulonglong2* yr0 = (const ulonglong2*)(xs + j*68);       // warp-uniform
        const ulonglong2* yr1 = (const ulonglong2*)(xs + (j+1)*68);   // broadcasts
        ull a0 = 0ull, a1 = 0ull, c0 = 0ull, c1 = 0ull;
        #pragma unroll
        for (int m = 0; m < 16; m++) {
            ulonglong2 y0 = yr0[m];
            ulonglong2 y1 = yr1[m];
            fma2(a0, xiu[2*m],   y0.x);
            fma2(a1, xiu[2*m+1], y0.y);
            fma2(c0, xiu[2*m],   y1.x);
            fma2(c1, xiu[2*m+1], y1.y);
        }
        float2 fa0 = upk(a0), fa1 = upk(a1), fc0 = upk(c0), fc1 = upk(c1);
        float pd0 = 2.0f*((fa0.x+fa0.y)+(fa1.x+fa1.y)) - xxi - xx[j];
        float pd1 = 2.0f*((fc0.x+fc0.y)+(fc1.x+fc1.y)) - xxi - xx[j+1];
        float thr = bv[K-1];
        if (pd0 > thr || pd1 > thr) {
            if (pd0 > bv[K-1]) {
                float v = pd0; int id = j;
                #pragma unroll
                for (int q = 0; q < K; q++) {
                    if (v > bv[q]) {
                        float tv = bv[q]; int tq = bix[q];
                        bv[q] = v; bix[q] = id;
                        v = tv;  id = tq;
                    }
                }
            }
            if (pd1 > bv[K-1]) {
                float v = pd1; int id = j + 1;
                #pragma unroll
                for (int q = 0; q < K; q++) {
                    if (v > bv[q]) {
                        float tv = bv[q]; int tq = bix[q];
                        bv[q] = v; bix[q] = id;
                        v = tv;  id = tq;
                    }
                }
            }
        }
    }
    float* ov = cv + (size_t)i*K;
    int*   oi = ci + (size_t)i*K;
    #pragma unroll
    for (int q = 0; q < K; q++) { ov[q] = bv[q]; oi[q] = bix[q]; }
}

__device__ __forceinline__ void jrange(int js, int& jlo, int& jhi) {
    jlo = (js == 0) ? 0 : (js == 1 ? 172 : 344);
    jhi = (js == 0) ? 172 : (js == 1 ? 344 : 512);
}

// ---------------- merge 3 partial sorted lists (strict->, ascending js = top_k order) ----------------
template<int K>
__device__ __forceinline__ void merge3(const float* __restrict__ cv,
                                       const int* __restrict__ ci,
                                       int b, int i, int* outIdx)
{
    float bv[K]; int bi[K];
    #pragma unroll
    for (int q = 0; q < K; q++) { bv[q] = -3e38f; bi[q] = 0; }
    for (int js = 0; js < 3; js++) {
        const float* v = cv + (((size_t)b*3 + js)*NN + i)*K;
        const int*   d = ci + (((size_t)b*3 + js)*NN + i)*K;
        #pragma unroll
        for (int q0 = 0; q0 < K; q0++) {
            float val = v[q0]; int id = d[q0];
            if (val > bv[K-1]) {
                #pragma unroll
                for (int q = 0; q < K; q++) {
                    if (val > bv[q]) {
                        float tv = bv[q]; int tq = bi[q];
                        bv[q] = val; bi[q] = id;
                        val = tv; id = tq;
                    }
                }
            }
        }
    }
    #pragma unroll
    for (int q = 0; q < K; q++) outIdx[q] = bi[q];
}

// ---------------- P'/Q' GEMM body (512 threads), BN folded, FFMA2, transposed out ----------------
__device__ __forceinline__ void pq_body(const float* __restrict__ xin, int b, int jq,
    const float* __restrict__ w, const float* __restrict__ gg,
    const float* __restrict__ bb2, const float* __restrict__ mm,
    const float* __restrict__ vv, float* smp)
{
    float* xs2   = smp;            // [64][128] x tile
    float* W2    = smp + 8192;     // [128][64] fused weights
    float* bias2 = smp + 16384;    // [128]
    float* sarr  = bias2 + 128;    // [64]
    int tid = threadIdx.x;

    if (tid < 64) sarr[tid] = gg[tid] * rsqrtf(vv[tid] + 1e-5f);
    __syncthreads();

    for (int idx = tid; idx < 128*64; idx += 512) {
        int r = idx >> 6, c = idx & 63;
        float val;
        if (r < 64) val = sarr[r] * w[r*128 + c];
        else { int o = r - 64; val = sarr[o] * (w[o*128 + 64 + c] - w[o*128 + c]); }
        W2[idx] = val;
    }
    if (tid < 128)
        bias2[tid] = (tid < 64) ? 0.f : (bb2[tid-64] - mm[tid-64]*sarr[tid-64]);

    const float* xb = xin + (size_t)b*NC*NN + jq*128;
    for (int idx = tid; idx < 64*128; idx += 512) {
        int c = idx >> 7, jj = idx & 127;
        xs2[idx] = xb[c*NN + jj];
    }
    __syncthreads();

    int rt = tid >> 5, ct = tid & 31;       // 16 x 32 thread grid
    int r0 = rt*8, j0 = ct*4;
    ull accp[8][2];
    #pragma unroll
    for (int u = 0; u < 8; u++) { accp[u][0] = 0ull; accp[u][1] = 0ull; }

    for (int kk = 0; kk < 64; kk++) {
        ull wp[8];
        #pragma unroll
        for (int u = 0; u < 8; u++) {
            float wv = W2[(r0+u)*64 + kk];
            wp[u] = pk2(wv, wv);
        }
        ulonglong2 xa = *(const ulonglong2*)(xs2 + kk*128 + j0);
        #pragma unroll
        for (int u = 0; u < 8; u++) {
            fma2(accp[u][0], wp[u], xa.x);
            fma2(accp[u][1], wp[u], xa.y);
        }
    }

    float a[8][4];
    #pragma unroll
    for (int u = 0; u < 8; u++) {
        float bsv = bias2[r0+u];
        float2 t0 = upk(accp[u][0]);
        float2 t1 = upk(accp[u][1]);
        a[u][0] = t0.x + bsv; a[u][1] = t0.y + bsv;
        a[u][2] = t1.x + bsv; a[u][3] = t1.y + bsv;
    }

    float* Ptb = g_PQ + (size_t)b*2*NO*NN;      // [512][64]
    float* Qtb = Ptb + (size_t)NN*NO;           // [512][64]
    #pragma unroll
    for (int v = 0; v < 4; v++) {
        int j = jq*128 + j0 + v;
        float* dst = (r0 < 64) ? (Ptb + (size_t)j*64 + r0)
                               : (Qtb + (size_t)j*64 + (r0-64));
        float4 o0 = make_float4(a[0][v], a[1][v], a[2][v], a[3][v]);
        float4 o1 = make_float4(a[4][v], a[5][v], a[6][v], a[7][v]);
        *(float4*)(dst)     = o0;
        *(float4*)(dst + 4) = o1;
    }
}

#define KNN_SMEM ((NN*68 + NN)*4)   // 141312 B (covers pq's 66KB too)

// ---------------- mega1: knn10(x0) + knn8(x1) + pq0, all independent after prep ----------------
__global__ __launch_bounds__(512) void k_mega1(
    const float* __restrict__ w0, const float* __restrict__ g0,
    const float* __restrict__ b0, const float* __restrict__ m0,
    const float* __restrict__ v0)
{
    extern __shared__ float smk[];
    int bb = blockIdx.x;
    if (bb < 3*NB) {
        int b = bb / 3, js = bb % 3;
        int jlo, jhi; jrange(js, jlo, jhi);
        knn_part<10>(g_x0 + (size_t)b*NC*NN,
                     g_c10v + ((size_t)b*3 + js)*NN*10,
                     g_c10i + ((size_t)b*3 + js)*NN*10,
                     jlo, jhi, smk, smk + NN*68);
    } else if (bb < 6*NB) {
        bb -= 3*NB;
        int b = bb / 3, js = bb % 3;
        int jlo, jhi; jrange(js, jlo, jhi);
        knn_part<8>(g_x1 + (size_t)b*NC*NN,
                    g_c8v + ((size_t)b*3 + js)*NN*8,
                    g_c8i + ((size_t)b*3 + js)*NN*8,
                    jlo, jhi, smk, smk + NN*68);
    } else {
        int pb = bb - 6*NB;                      // [0, 384)
        pq_body(g_x0, pb >> 2, pb & 3, w0, g0, b0, m0, v0, smk);
    }
}

// ---------------- mega2: knn10(x1e) + pq1, both independent after erase1 ----------------
__global__ __launch_bounds__(512) void k_mega2(
    const float* __restrict__ w1, const float* __restrict__ g1,
    const float* __restrict__ b1, const float* __restrict__ m1,
    const float* __restrict__ v1)
{
    extern __shared__ float smk[];
    int bb = blockIdx.x;
    if (bb < 3*NB) {
        int b = bb / 3, js = bb % 3;
        int jlo, jhi; jrange(js, jlo, jhi);
        knn_part<10>(g_x1e + (size_t)b*NC*NN,
                     g_c10v + ((size_t)b*3 + js)*NN*10,
                     g_c10i + ((size_t)b*3 + js)*NN*10,
                     jlo, jhi, smk, smk + NN*68);
    } else {
        int pb = bb - 3*NB;
        pq_body(g_x1e, pb >> 2, pb & 3, w1, g1, b1, m1, v1, smk);
    }
}

// ---------------- gather-max over k (inline merge10) + lrelu + partial max/mean ----------------
__global__ __launch_bounds__(256) void k_gmax()
{
    int b = blockIdx.x, jq = blockIdx.y, tid = threadIdx.x;
    int w = tid >> 5, l = tid & 31;
    const float* Pt = g_PQ + (size_t)b*2*NO*NN;
    const float* Qt = Pt + (size_t)NN*NO;

    __shared__ int ids[128][10];
    if (tid < 128) merge3<10>(g_c10v, g_c10i, b, jq*128 + tid, ids[tid]);
    __syncthreads();

    float mx0 = -3e38f, mx1 = -3e38f, s0 = 0.f, s1 = 0.f;
    #pragma unroll 2
    for (int p = 0; p < 16; p++) {
        int il = w*16 + p;
        int i = jq*128 + il;
        const int* ip = ids[il];
        float a0 = -3e38f, a1 = -3e38f;
        #pragma unroll
        for (int kk = 0; kk < 10; kk++) {
            int nb = ip[kk];                               // uniform -> broadcast
            float2 pv = *(const float2*)(Pt + (size_t)nb*64 + 2*l);
            a0 = fmaxf(a0, pv.x);
            a1 = fmaxf(a1, pv.y);
        }
        float2 q = *(const float2*)(Qt + (size_t)i*64 + 2*l);
        float y0 = a0 + q.x; y0 = (y0 > 0.f) ? y0 : 0.2f*y0;
        float y1 = a1 + q.y; y1 = (y1 > 0.f) ? y1 : 0.2f*y1;
        mx0 = fmaxf(mx0, y0); s0 += y0;
        mx1 = fmaxf(mx1, y1); s1 += y1;
    }

    __shared__ float sred[8][128];
    sred[w][2*l]      = mx0;
    sred[w][2*l+1]    = mx1;
    sred[w][64+2*l]   = s0;
    sred[w][64+2*l+1] = s1;
    __syncthreads();
    if (tid < 128) {
        float v;
        if (tid < 64) {
            v = sred[0][tid];
            #pragma unroll
            for (int ww = 1; ww < 8; ww++) v = fmaxf(v, sred[ww][tid]);
        } else {
            v = sred[0][tid];
            #pragma unroll
            for (int ww = 1; ww < 8; ww++) v += sred[ww][tid];
        }
        g_part[((size_t)b*4 + jq)*128 + tid] = v;
    }
}

// ---------------- final reduction over the 4 point-chunks ----------------
__global__ __launch_bounds__(128) void k_fin(float* __restrict__ out, int accumulate)
{
    int b = blockIdx.x, tid = threadIdx.x;
    const float* pp = g_part + (size_t)b*4*128;
    float v;
    if (tid < 64) {
        v = pp[tid];
        #pragma unroll
        for (int jq = 1; jq < 4; jq++) v = fmaxf(v, pp[jq*128 + tid]);
    } else {
        v = pp[tid];
        #pragma unroll
        for (int jq = 1; jq < 4; jq++) v += pp[jq*128 + tid];
        v *= (1.0f/NN);
    }
    if (accumulate) out[b*128 + tid] += v;
    else            out[b*128 + tid]  = v;
}

// ---------------- corre_binar (inline merge8): q, f, fk, argmax, masks ----------------
__global__ __launch_bounds__(512) void k_corre(const float* __restrict__ w_red,
                                               const float* __restrict__ outv)
{
    __shared__ float qv[64];
    __shared__ float fs[NN];
    __shared__ float rv[NN];
    __shared__ int   ri[NN];
    __shared__ int   ri8[NN][8];
    int b = blockIdx.x, tid = threadIdx.x;
    if (tid < 64) {
        const float* xv = outv + b*128;    // x0_vec == p0 max-half
        float a = 0.f;
        for (int c = 0; c < 64; c++) a = fmaf(w_red[tid*64 + c], xv[c], a);
        qv[tid] = a;
    }
    merge3<8>(g_c8v, g_c8i, b, tid, ri8[tid]);
    __syncthreads();
    const float* x1b = g_x1 + (size_t)b*NC*NN;
    float f = 0.f;
    for (int c = 0; c < 64; c++) f = fmaf(qv[c], x1b[c*NN + tid], f);
    f *= 0.125f;
    fs[tid] = f;
    g_f[b*NN + tid] = f;
    __syncthreads();
    float fk = f;
    #pragma unroll
    for (int kk = 0; kk < 8; kk++) fk += fs[ri8[tid][kk]];
    rv[tid] = fk; ri[tid] = tid;
    __syncthreads();
    for (int s2 = 256; s2 > 0; s2 >>= 1) {   // argmax, ties -> lowest index
        if (tid < s2) {
            float a = rv[tid], b2 = rv[tid + s2];
            int ia = ri[tid], ib2 = ri[tid + s2];
            if (b2 > a || (b2 == a && ib2 < ia)) { rv[tid] = b2; ri[tid] = ib2; }
        }
        __syncthreads();
    }
    int widx = ri[0];
    g_msk[b*NN + tid] = 1.0f;
    __syncthreads();
    if (tid == 0) g_msk[b*NN + widx] = 0.f;
    if (tid < 8)  g_msk[b*NN + ri8[widx][tid]] = 0.f;
}

// ---------------- erase1 (masked softmax attention + conv_erase) ----------------
__global__ __launch_bounds__(512) void k_erase1(
    const float* __restrict__ w_e, const float* __restrict__ b_e,
    const float* __restrict__ g_e, const float* __restrict__ be_e,
    const float* __restrict__ m_e, const float* __restrict__ v_e)
{
    __shared__ float smw[NN];
    __shared__ float red[NN];
    __shared__ float msk[NN];
    __shared__ float res[64];
    __shared__ float yb[64];
    int b = blockIdx.x, tid = threadIdx.x;
    const float* x1b = g_x1 + (size_t)b*NC*NN;

    float M = g_msk[b*NN + tid];
    float f = g_f[b*NN + tid];
    msk[tid] = M;
    float z = f - (1.0f - M)*1e8f;
    red[tid] = z;
    __syncthreads();
    for (int s2 = 256; s2 > 0; s2 >>= 1) {
        if (tid < s2) red[tid] = fmaxf(red[tid], red[tid + s2]);
        __syncthreads();
    }
    float zmax = red[0];
    __syncthreads();
    float e = expf(z - zmax);
    red[tid] = e;
    __syncthreads();
    for (int s2 = 256; s2 > 0; s2 >>= 1) {
        if (tid < s2) red[tid] += red[tid + s2];
        __syncthreads();
    }
    float esum = red[0];
    smw[tid] = e / esum;
    __syncthreads();

    int ch = tid >> 3, ln = tid & 7;
    float a = 0.f;
    for (int i = ln; i < NN; i += 8) a = fmaf(x1b[ch*NN + i], smw[i], a);
    a += __shfl_down_sync(0xffffffffu, a, 1, 8);
    a += __shfl_down_sync(0xffffffffu, a, 2, 8);
    a += __shfl_down_sync(0xffffffffu, a, 4, 8);
    if (ln == 0) res[ch] = a;
    __syncthreads();

    if (tid < 64) {
        float y = b_e[tid];
        for (int c = 0; c < 64; c++) y = fmaf(w_e[tid*64 + c], res[c], y);
        float sc = g_e[tid]*rsqrtf(v_e[tid] + 1e-5f);
        yb[tid] = (y - m_e[tid])*sc + be_e[tid];
    }
    __syncthreads();

    float* xo = g_x1e + (size_t)b*NC*NN;
    for (int idx = tid; idx < NC*NN; idx += 512) {
        int c = idx >> 9, i = idx & 511;
        xo[idx] = x1b[idx]*msk[i] + yb[c];
    }
}

// ---------------- launcher ----------------
extern "C" void kernel_launch(void* const* d_in, const int* in_sizes, int n_in,
                              void* d_out, int out_size)
{
    const float* x        = (const float*)d_in[0];
    const float* w_reduce = (const float*)d_in[1];
    const float* w_erase  = (const float*)d_in[2];
    const float* b_erase  = (const float*)d_in[3];
    const float* g_erase  = (const float*)d_in[4];
    const float* be_erase = (const float*)d_in[5];
    const float* m_erase  = (const float*)d_in[6];
    const float* v_erase  = (const float*)d_in[7];
    const float* w0 = (const float*)d_in[8];
    const float* g0 = (const float*)d_in[9];
    const float* b0 = (const float*)d_in[10];
    const float* m0 = (const float*)d_in[11];
    const float* v0 = (const float*)d_in[12];
    const float* w1 = (const float*)d_in[13];
    const float* g1 = (const float*)d_in[14];
    const float* b1 = (const float*)d_in[15];
    const float* m1 = (const float*)d_in[16];
    const float* v1 = (const float*)d_in[17];
    float* out = (float*)d_out;

    cudaFuncSetAttribute(k_mega1, cudaFuncAttributeMaxDynamicSharedMemorySize, KNN_SMEM);
    cudaFuncSetAttribute(k_mega2, cudaFuncAttributeMaxDynamicSharedMemorySize, KNN_SMEM);

    k_prep<<<NB, 256>>>(x, w_erase, b_erase, g_erase, be_erase, m_erase, v_erase);
    k_mega1<<<6*NB + 4*NB, 512, KNN_SMEM>>>(w0, g0, b0, m0, v0);  // knn10(x0)+knn8(x1)+pq0
    k_gmax<<<dim3(NB,4), 256>>>();                                // merge10 inline + partials
    k_fin<<<NB, 128>>>(out, 0);                                   // p0 -> out (x0_vec)
    k_corre<<<NB, 512>>>(w_reduce, out);                          // merge8 inline; masks, f
    k_erase1<<<NB, 512>>>(w_erase, b_erase, g_erase, be_erase, m_erase, v_erase);
    k_mega2<<<3*NB + 4*NB, 512, KNN_SMEM>>>(w1, g1, b1, m1, v1);  // knn10(x1e)+pq1
    k_gmax<<<dim3(NB,4), 256>>>();
    k_fin<<<NB, 128>>>(out, 1);                                   // out += p1
}